// round 6
// baseline (speedup 1.0000x reference)
#include <cuda_runtime.h>

#define NN 100000
#define NE 3200000
#define NF 128
#define NH 16
#define MH 100
#define NC 12
#define NG 512

// Scratch (allocation-free per harness rules)
__device__ __align__(16) float g_dinv[NN];
__device__ __align__(16) float g_hA[NN * NH];
__device__ __align__(16) float g_hB[NN * NH];
__device__ __align__(16) float g_pool[NG * NH];
__device__ __align__(16) int   g_src32[NE];
__device__ __align__(16) int   g_dst32[NE];
__device__ int g_is64;

__device__ __forceinline__ void red_add_v4(float* addr, float4 v) {
    asm volatile("red.global.add.v4.f32 [%0], {%1,%2,%3,%4};"
                 :: "l"(addr), "f"(v.x), "f"(v.y), "f"(v.z), "f"(v.w)
                 : "memory");
}

// ---------------------------------------------------------------------------
// 0) detect whether integer inputs are int64 or int32 in device memory.
//    For int64 values < 2^31, every odd 32-bit word is 0. For random int32
//    node indices, 16 consecutive odd words all being zero is ~impossible.
__global__ void k_detect(const int* __restrict__ ei_raw) {
    int ok = 1;
    #pragma unroll
    for (int i = 1; i < 32; i += 2)
        if (ei_raw[i] != 0) ok = 0;
    g_is64 = ok;
}

// 1) init: deg = 1 (self loop), pool = 0
__global__ void k_init() {
    int i = blockIdx.x * blockDim.x + threadIdx.x;
    if (i < NN) g_dinv[i] = 1.0f;
    if (i < NG * NH) g_pool[i] = 0.0f;
}

// 2) fused: index conversion (either dtype) + degree count (dst side).
//    2 edges per thread, vectorized loads.
__global__ void k_cvt_deg(const void* __restrict__ ei) {
    int e = (blockIdx.x * blockDim.x + threadIdx.x) * 2;
    if (e >= NE) return;  // NE % 2 == 0
    int2 s32, d32;
    if (g_is64) {
        const long long* p = (const long long*)ei;
        longlong2 s = *(const longlong2*)(p + e);
        longlong2 d = *(const longlong2*)(p + NE + e);
        s32 = make_int2((int)s.x, (int)s.y);
        d32 = make_int2((int)d.x, (int)d.y);
    } else {
        const int* p = (const int*)ei;
        s32 = *(const int2*)(p + e);
        d32 = *(const int2*)(p + NE + e);
    }
    *(int2*)(g_src32 + e) = s32;
    *(int2*)(g_dst32 + e) = d32;
    atomicAdd(&g_dinv[d32.x], 1.0f);
    atomicAdd(&g_dinv[d32.y], 1.0f);
}

// 3) deg -> 1/sqrt(deg) in place (deg >= 1 always)
__global__ void k_rsqrt() {
    int i = blockIdx.x * blockDim.x + threadIdx.x;
    if (i < NN) g_dinv[i] = rsqrtf(g_dinv[i]);
}

// ---------------------------------------------------------------------------
// 4) g_hA = x @ W1   ([100000,128] @ [128,16]); 4 rows per thread, W1 in smem.
__global__ void k_xw1(const float* __restrict__ x, const float* __restrict__ W1) {
    __shared__ float sW[NF * NH];
    int t = threadIdx.x;
    for (int i = t; i < NF * NH; i += blockDim.x) sW[i] = W1[i];
    __syncthreads();

    int r0 = (blockIdx.x * blockDim.x + t) * 4;
    if (r0 >= NN) return;   // NN % 4 == 0

    float acc[4][NH];
    #pragma unroll
    for (int r = 0; r < 4; r++)
        #pragma unroll
        for (int m = 0; m < NH; m++) acc[r][m] = 0.0f;

    const float4* x4 = (const float4*)x;
    const float4* sW4 = (const float4*)sW;

    for (int k4 = 0; k4 < NF / 4; k4++) {
        float4 xv[4];
        #pragma unroll
        for (int r = 0; r < 4; r++)
            xv[r] = x4[(size_t)(r0 + r) * (NF / 4) + k4];

        #pragma unroll
        for (int j = 0; j < 4; j++) {
            int k = k4 * 4 + j;
            #pragma unroll
            for (int m4 = 0; m4 < NH / 4; m4++) {
                float4 wv = sW4[k * (NH / 4) + m4];
                #pragma unroll
                for (int r = 0; r < 4; r++) {
                    float xs = (j == 0) ? xv[r].x : (j == 1) ? xv[r].y
                             : (j == 2) ? xv[r].z : xv[r].w;
                    acc[r][m4 * 4 + 0] += xs * wv.x;
                    acc[r][m4 * 4 + 1] += xs * wv.y;
                    acc[r][m4 * 4 + 2] += xs * wv.z;
                    acc[r][m4 * 4 + 3] += xs * wv.w;
                }
            }
        }
    }

    #pragma unroll
    for (int r = 0; r < 4; r++) {
        float4* o = (float4*)(g_hA + (size_t)(r0 + r) * NH);
        #pragma unroll
        for (int m4 = 0; m4 < NH / 4; m4++)
            o[m4] = make_float4(acc[r][m4 * 4 + 0], acc[r][m4 * 4 + 1],
                                acc[r][m4 * 4 + 2], acc[r][m4 * 4 + 3]);
    }
}

// ---------------------------------------------------------------------------
// 5) non-atomic init of scatter output: out = b + dinv[n]^2 * h[n] (self loop)
__global__ void k_self(const float* __restrict__ b) {
    int n = blockIdx.x * blockDim.x + threadIdx.x;
    if (n >= NN) return;
    float di = g_dinv[n];
    float d2 = di * di;
    const float4* hr = (const float4*)(g_hA + (size_t)n * NH);
    float4* orow = (float4*)(g_hB + (size_t)n * NH);
    const float4* b4 = (const float4*)b;
    #pragma unroll
    for (int c = 0; c < NH / 4; c++) {
        float4 hv = hr[c];
        float4 bv = b4[c];
        orow[c] = make_float4(bv.x + d2 * hv.x, bv.y + d2 * hv.y,
                              bv.z + d2 * hv.z, bv.w + d2 * hv.w);
    }
}

// 6) edge scatter: g_hB[dst] += dinv[src]*dinv[dst] * g_hA[src]
//    2 edges per thread, int32 indices, vector RED.
__global__ void k_scatter() {
    int e = (blockIdx.x * blockDim.x + threadIdx.x) * 2;
    if (e >= NE) return;  // NE % 2 == 0
    int2 s = *(const int2*)(g_src32 + e);
    int2 d = *(const int2*)(g_dst32 + e);

    float nm0 = g_dinv[s.x] * g_dinv[d.x];
    float nm1 = g_dinv[s.y] * g_dinv[d.y];

    const float4* h0 = (const float4*)(g_hA + (size_t)s.x * NH);
    const float4* h1 = (const float4*)(g_hA + (size_t)s.y * NH);
    float* o0 = g_hB + (size_t)d.x * NH;
    float* o1 = g_hB + (size_t)d.y * NH;

    #pragma unroll
    for (int c = 0; c < NH / 4; c++) {
        float4 v0 = __ldg(h0 + c);
        float4 v1 = __ldg(h1 + c);
        red_add_v4(o0 + c * 4,
                   make_float4(v0.x * nm0, v0.y * nm0, v0.z * nm0, v0.w * nm0));
        red_add_v4(o1 + c * 4,
                   make_float4(v1.x * nm1, v1.y * nm1, v1.z * nm1, v1.w * nm1));
    }
}

// ---------------------------------------------------------------------------
// 7) g_hA = relu(g_hB) @ W2   (per-node 16x16)
__global__ void k_relu_w2(const float* __restrict__ W2) {
    __shared__ float sW[NH * NH];
    int t = threadIdx.x;
    if (t < NH * NH) sW[t] = W2[t];
    __syncthreads();

    int n = blockIdx.x * blockDim.x + t;
    if (n >= NN) return;

    float hv[NH];
    const float4* hr = (const float4*)(g_hB + (size_t)n * NH);
    #pragma unroll
    for (int c = 0; c < NH / 4; c++) {
        float4 v = hr[c];
        hv[c * 4 + 0] = fmaxf(v.x, 0.0f);
        hv[c * 4 + 1] = fmaxf(v.y, 0.0f);
        hv[c * 4 + 2] = fmaxf(v.z, 0.0f);
        hv[c * 4 + 3] = fmaxf(v.w, 0.0f);
    }

    float acc[NH];
    #pragma unroll
    for (int m = 0; m < NH; m++) acc[m] = 0.0f;
    #pragma unroll
    for (int k = 0; k < NH; k++) {
        float xs = hv[k];
        #pragma unroll
        for (int m = 0; m < NH; m++) acc[m] += xs * sW[k * NH + m];
    }

    float4* o = (float4*)(g_hA + (size_t)n * NH);
    #pragma unroll
    for (int m4 = 0; m4 < NH / 4; m4++)
        o[m4] = make_float4(acc[m4 * 4 + 0], acc[m4 * 4 + 1],
                            acc[m4 * 4 + 2], acc[m4 * 4 + 3]);
}

// ---------------------------------------------------------------------------
// 8) pooling: g_pool[batch[n]] += relu(g_hB[n])
__global__ void k_pool(const void* __restrict__ batch) {
    int n = blockIdx.x * blockDim.x + threadIdx.x;
    if (n >= NN) return;
    int b;
    if (g_is64) b = (int)((const long long*)batch)[n];
    else        b = ((const int*)batch)[n];
    const float4* hr = (const float4*)(g_hB + (size_t)n * NH);
    float* p = g_pool + (size_t)b * NH;
    #pragma unroll
    for (int c = 0; c < NH / 4; c++) {
        float4 v = hr[c];
        red_add_v4(p + c * 4,
                   make_float4(fmaxf(v.x, 0.0f), fmaxf(v.y, 0.0f),
                               fmaxf(v.z, 0.0f), fmaxf(v.w, 0.0f)));
    }
}

// ---------------------------------------------------------------------------
// 9) MLP head: out = relu(relu(pool) @ lw1 + lb1) @ lw2 + lb2
__global__ void k_mlp(const float* __restrict__ lw1, const float* __restrict__ lb1,
                      const float* __restrict__ lw2, const float* __restrict__ lb2,
                      float* __restrict__ out) {
    __shared__ float sg[NH];
    __shared__ float sh[MH];
    int g = blockIdx.x;
    int t = threadIdx.x;
    if (t < NH) sg[t] = fmaxf(g_pool[(size_t)g * NH + t], 0.0f);
    __syncthreads();
    if (t < MH) {
        float a = lb1[t];
        #pragma unroll
        for (int i = 0; i < NH; i++) a += sg[i] * lw1[i * MH + t];
        sh[t] = fmaxf(a, 0.0f);
    }
    __syncthreads();
    if (t < NC) {
        float a = lb2[t];
        #pragma unroll 4
        for (int i = 0; i < MH; i++) a += sh[i] * lw2[i * NC + t];
        out[(size_t)g * NC + t] = a;
    }
}

// ---------------------------------------------------------------------------
extern "C" void kernel_launch(void* const* d_in, const int* in_sizes, int n_in,
                              void* d_out, int out_size) {
    const float* x     = (const float*)d_in[0];
    const void*  ei    = d_in[1];
    const void*  batch = d_in[2];
    const float* W1    = (const float*)d_in[3];
    const float* b1    = (const float*)d_in[4];
    const float* W2    = (const float*)d_in[5];
    const float* b2    = (const float*)d_in[6];
    const float* lw1   = (const float*)d_in[7];
    const float* lb1   = (const float*)d_in[8];
    const float* lw2   = (const float*)d_in[9];
    const float* lb2   = (const float*)d_in[10];
    float* out = (float*)d_out;

    const int T = 256;
    const int gN = (NN + T - 1) / T;
    const int gE2 = (NE / 2 + T - 1) / T;

    k_detect<<<1, 1>>>((const int*)ei);
    k_init<<<gN, T>>>();
    k_cvt_deg<<<gE2, T>>>(ei);
    k_rsqrt<<<gN, T>>>();
    k_xw1<<<(NN / 4 + T - 1) / T, T>>>(x, W1);

    // layer 1: hB = b1 + scatter(norm * hA)
    k_self<<<gN, T>>>(b1);
    k_scatter<<<gE2, T>>>();

    // hA = relu(hB) @ W2
    k_relu_w2<<<gN, T>>>(W2);

    // layer 2: hB = b2 + scatter(norm * hA)
    k_self<<<gN, T>>>(b2);
    k_scatter<<<gE2, T>>>();

    // pool + head
    k_pool<<<gN, T>>>(batch);
    k_mlp<<<NG, 128>>>(lw1, lb1, lw2, lb2, out);

    (void)in_sizes; (void)n_in; (void)out_size;
}

// round 9
// speedup vs baseline: 1.5908x; 1.5908x over previous
#include <cuda_runtime.h>

#define NN 100000
#define NE 3200000
#define NF 128
#define NH 16
#define MH 100
#define NC 12
#define NG 512

#define SCAN_CHUNK 512
#define NBLK ((NN + SCAN_CHUNK - 1) / SCAN_CHUNK)   // 196

// Scratch (allocation-free per harness rules)
__device__ __align__(16) float  g_dinv[NN];
__device__ __align__(16) int    g_degi[NN];
__device__ __align__(16) int    g_off[NN];
__device__ __align__(16) int    g_cursor[NN];
__device__ __align__(16) int    g_bsum[NBLK];
__device__ __align__(16) int    g_boff[NBLK];
__device__ __align__(16) float  g_hA[NN * NH];
__device__ __align__(16) float  g_hB[NN * NH];
__device__ __align__(16) float  g_pool[NG * NH];
__device__ __align__(16) int    g_src32[NE];
__device__ __align__(16) int    g_dst32[NE];
__device__ __align__(16) float2 g_epack[NE];   // {src bits, norm}
__device__ int g_is64;

__device__ __forceinline__ void red_add_v4(float* addr, float4 v) {
    asm volatile("red.global.add.v4.f32 [%0], {%1,%2,%3,%4};"
                 :: "l"(addr), "f"(v.x), "f"(v.y), "f"(v.z), "f"(v.w)
                 : "memory");
}

// ---------------------------------------------------------------------------
// 0) dtype probe: int64 vs int32 integer inputs (odd 32-bit words all zero).
__global__ void k_detect(const int* __restrict__ ei_raw) {
    int ok = 1;
    #pragma unroll
    for (int i = 1; i < 32; i += 2)
        if (ei_raw[i] != 0) ok = 0;
    g_is64 = ok;
}

// 1) init: degi = 0, pool = 0
__global__ void k_init() {
    int i = blockIdx.x * blockDim.x + threadIdx.x;
    if (i < NN) g_degi[i] = 0;
    if (i < NG * NH) g_pool[i] = 0.0f;
}

// 2) fused: index conversion + degree histogram (dst side). 2 edges/thread.
__global__ void k_cvt_deg(const void* __restrict__ ei) {
    int e = (blockIdx.x * blockDim.x + threadIdx.x) * 2;
    if (e >= NE) return;  // NE % 2 == 0
    int2 s32, d32;
    if (g_is64) {
        const long long* p = (const long long*)ei;
        longlong2 s = *(const longlong2*)(p + e);
        longlong2 d = *(const longlong2*)(p + NE + e);
        s32 = make_int2((int)s.x, (int)s.y);
        d32 = make_int2((int)d.x, (int)d.y);
    } else {
        const int* p = (const int*)ei;
        s32 = *(const int2*)(p + e);
        d32 = *(const int2*)(p + NE + e);
    }
    *(int2*)(g_src32 + e) = s32;
    *(int2*)(g_dst32 + e) = d32;
    atomicAdd(&g_degi[d32.x], 1);
    atomicAdd(&g_degi[d32.y], 1);
}

// 3) dinv = rsqrt(deg_real + 1)  (+1 = self loop)
__global__ void k_rsqrt() {
    int i = blockIdx.x * blockDim.x + threadIdx.x;
    if (i < NN) g_dinv[i] = rsqrtf((float)(g_degi[i] + 1));
}

// ---------------------------------------------------------------------------
// 4) exclusive scan of g_degi -> g_off  (3 kernels)
__global__ void k_scan1() {
    __shared__ int s[256];
    int t = threadIdx.x, b = blockIdx.x;
    int i0 = b * SCAN_CHUNK + t * 2;
    int a = (i0     < NN) ? g_degi[i0]     : 0;
    int c = (i0 + 1 < NN) ? g_degi[i0 + 1] : 0;
    int pair = a + c;
    s[t] = pair;
    __syncthreads();
    for (int ofs = 1; ofs < 256; ofs <<= 1) {
        int v = (t >= ofs) ? s[t - ofs] : 0;
        __syncthreads();
        s[t] += v;
        __syncthreads();
    }
    int excl = s[t] - pair;
    if (i0     < NN) g_off[i0]     = excl;
    if (i0 + 1 < NN) g_off[i0 + 1] = excl + a;
    if (t == 255) g_bsum[b] = s[255];
}

__global__ void k_scan2() {
    __shared__ int s[256];
    int t = threadIdx.x;
    int v = (t < NBLK) ? g_bsum[t] : 0;
    s[t] = v;
    __syncthreads();
    for (int ofs = 1; ofs < 256; ofs <<= 1) {
        int u = (t >= ofs) ? s[t - ofs] : 0;
        __syncthreads();
        s[t] += u;
        __syncthreads();
    }
    if (t < NBLK) g_boff[t] = s[t] - v;  // exclusive
}

__global__ void k_scan3() {
    int i = blockIdx.x * blockDim.x + threadIdx.x;
    if (i >= NN) return;
    int o = g_off[i] + g_boff[i / SCAN_CHUNK];
    g_off[i] = o;
    g_cursor[i] = o;
}

// 5) placement: bucket edges by dst, pack (src, norm)
__global__ void k_place() {
    int e = blockIdx.x * blockDim.x + threadIdx.x;
    if (e >= NE) return;
    int s = g_src32[e];
    int d = g_dst32[e];
    int pos = atomicAdd(&g_cursor[d], 1);
    float nm = g_dinv[s] * g_dinv[d];
    g_epack[pos] = make_float2(__int_as_float(s), nm);
}

// ---------------------------------------------------------------------------
// 6) g_hA = x @ W1   ([100000,128] @ [128,16]); 4 rows per thread, W1 in smem.
__global__ void k_xw1(const float* __restrict__ x, const float* __restrict__ W1) {
    __shared__ float sW[NF * NH];
    int t = threadIdx.x;
    for (int i = t; i < NF * NH; i += blockDim.x) sW[i] = W1[i];
    __syncthreads();

    int r0 = (blockIdx.x * blockDim.x + t) * 4;
    if (r0 >= NN) return;   // NN % 4 == 0

    float acc[4][NH];
    #pragma unroll
    for (int r = 0; r < 4; r++)
        #pragma unroll
        for (int m = 0; m < NH; m++) acc[r][m] = 0.0f;

    const float4* x4 = (const float4*)x;
    const float4* sW4 = (const float4*)sW;

    for (int k4 = 0; k4 < NF / 4; k4++) {
        float4 xv[4];
        #pragma unroll
        for (int r = 0; r < 4; r++)
            xv[r] = x4[(size_t)(r0 + r) * (NF / 4) + k4];

        #pragma unroll
        for (int j = 0; j < 4; j++) {
            int k = k4 * 4 + j;
            #pragma unroll
            for (int m4 = 0; m4 < NH / 4; m4++) {
                float4 wv = sW4[k * (NH / 4) + m4];
                #pragma unroll
                for (int r = 0; r < 4; r++) {
                    float xs = (j == 0) ? xv[r].x : (j == 1) ? xv[r].y
                             : (j == 2) ? xv[r].z : xv[r].w;
                    acc[r][m4 * 4 + 0] += xs * wv.x;
                    acc[r][m4 * 4 + 1] += xs * wv.y;
                    acc[r][m4 * 4 + 2] += xs * wv.z;
                    acc[r][m4 * 4 + 3] += xs * wv.w;
                }
            }
        }
    }

    #pragma unroll
    for (int r = 0; r < 4; r++) {
        float4* o = (float4*)(g_hA + (size_t)(r0 + r) * NH);
        #pragma unroll
        for (int m4 = 0; m4 < NH / 4; m4++)
            o[m4] = make_float4(acc[r][m4 * 4 + 0], acc[r][m4 * 4 + 1],
                                acc[r][m4 * 4 + 2], acc[r][m4 * 4 + 3]);
    }
}

// ---------------------------------------------------------------------------
// 7) CSR gather: g_hB[n] = bias + dinv[n]^2*g_hA[n] + sum_e nm*g_hA[src]
//    4 threads per node (one float4 chunk each); epack loads broadcast.
__global__ void k_gather(const float* __restrict__ bias) {
    int t = blockIdx.x * blockDim.x + threadIdx.x;
    if (t >= NN * 4) return;
    int n = t >> 2;
    int c = t & 3;

    float di = g_dinv[n];
    float d2 = di * di;
    const float4* hin = (const float4*)g_hA;
    float4 h0 = hin[n * 4 + c];
    float4 bv = ((const float4*)bias)[c];
    float4 acc = make_float4(bv.x + d2 * h0.x, bv.y + d2 * h0.y,
                             bv.z + d2 * h0.z, bv.w + d2 * h0.w);

    int beg = g_off[n];
    int end = beg + g_degi[n];
    for (int e = beg; e < end; e++) {
        float2 p = __ldg(&g_epack[e]);
        int s = __float_as_int(p.x);
        float nm = p.y;
        float4 v = __ldg(&hin[s * 4 + c]);
        acc.x += nm * v.x;
        acc.y += nm * v.y;
        acc.z += nm * v.z;
        acc.w += nm * v.w;
    }
    ((float4*)g_hB)[n * 4 + c] = acc;
}

// ---------------------------------------------------------------------------
// 8) g_hA = relu(g_hB) @ W2   (per-node 16x16)
__global__ void k_relu_w2(const float* __restrict__ W2) {
    __shared__ float sW[NH * NH];
    int t = threadIdx.x;
    if (t < NH * NH) sW[t] = W2[t];
    __syncthreads();

    int n = blockIdx.x * blockDim.x + t;
    if (n >= NN) return;

    float hv[NH];
    const float4* hr = (const float4*)(g_hB + (size_t)n * NH);
    #pragma unroll
    for (int c = 0; c < NH / 4; c++) {
        float4 v = hr[c];
        hv[c * 4 + 0] = fmaxf(v.x, 0.0f);
        hv[c * 4 + 1] = fmaxf(v.y, 0.0f);
        hv[c * 4 + 2] = fmaxf(v.z, 0.0f);
        hv[c * 4 + 3] = fmaxf(v.w, 0.0f);
    }

    float acc[NH];
    #pragma unroll
    for (int m = 0; m < NH; m++) acc[m] = 0.0f;
    #pragma unroll
    for (int k = 0; k < NH; k++) {
        float xs = hv[k];
        #pragma unroll
        for (int m = 0; m < NH; m++) acc[m] += xs * sW[k * NH + m];
    }

    float4* o = (float4*)(g_hA + (size_t)n * NH);
    #pragma unroll
    for (int m4 = 0; m4 < NH / 4; m4++)
        o[m4] = make_float4(acc[m4 * 4 + 0], acc[m4 * 4 + 1],
                            acc[m4 * 4 + 2], acc[m4 * 4 + 3]);
}

// ---------------------------------------------------------------------------
// 9) pooling: g_pool[batch[n]] += relu(g_hB[n])
__global__ void k_pool(const void* __restrict__ batch) {
    int n = blockIdx.x * blockDim.x + threadIdx.x;
    if (n >= NN) return;
    int b;
    if (g_is64) b = (int)((const long long*)batch)[n];
    else        b = ((const int*)batch)[n];
    const float4* hr = (const float4*)(g_hB + (size_t)n * NH);
    float* p = g_pool + (size_t)b * NH;
    #pragma unroll
    for (int c = 0; c < NH / 4; c++) {
        float4 v = hr[c];
        red_add_v4(p + c * 4,
                   make_float4(fmaxf(v.x, 0.0f), fmaxf(v.y, 0.0f),
                               fmaxf(v.z, 0.0f), fmaxf(v.w, 0.0f)));
    }
}

// ---------------------------------------------------------------------------
// 10) MLP head: out = relu(relu(pool) @ lw1 + lb1) @ lw2 + lb2
__global__ void k_mlp(const float* __restrict__ lw1, const float* __restrict__ lb1,
                      const float* __restrict__ lw2, const float* __restrict__ lb2,
                      float* __restrict__ out) {
    __shared__ float sg[NH];
    __shared__ float sh[MH];
    int g = blockIdx.x;
    int t = threadIdx.x;
    if (t < NH) sg[t] = fmaxf(g_pool[(size_t)g * NH + t], 0.0f);
    __syncthreads();
    if (t < MH) {
        float a = lb1[t];
        #pragma unroll
        for (int i = 0; i < NH; i++) a += sg[i] * lw1[i * MH + t];
        sh[t] = fmaxf(a, 0.0f);
    }
    __syncthreads();
    if (t < NC) {
        float a = lb2[t];
        #pragma unroll 4
        for (int i = 0; i < MH; i++) a += sh[i] * lw2[i * NC + t];
        out[(size_t)g * NC + t] = a;
    }
}

// ---------------------------------------------------------------------------
extern "C" void kernel_launch(void* const* d_in, const int* in_sizes, int n_in,
                              void* d_out, int out_size) {
    const float* x     = (const float*)d_in[0];
    const void*  ei    = d_in[1];
    const void*  batch = d_in[2];
    const float* W1    = (const float*)d_in[3];
    const float* b1    = (const float*)d_in[4];
    const float* W2    = (const float*)d_in[5];
    const float* b2    = (const float*)d_in[6];
    const float* lw1   = (const float*)d_in[7];
    const float* lb1   = (const float*)d_in[8];
    const float* lw2   = (const float*)d_in[9];
    const float* lb2   = (const float*)d_in[10];
    float* out = (float*)d_out;

    const int T = 256;
    const int gN  = (NN + T - 1) / T;
    const int gE  = (NE + T - 1) / T;
    const int gE2 = (NE / 2 + T - 1) / T;
    const int gG  = (NN * 4 + T - 1) / T;

    k_detect<<<1, 1>>>((const int*)ei);
    k_init<<<gN, T>>>();
    k_cvt_deg<<<gE2, T>>>(ei);
    k_rsqrt<<<gN, T>>>();

    // CSR build
    k_scan1<<<NBLK, 256>>>();
    k_scan2<<<1, 256>>>();
    k_scan3<<<gN, T>>>();
    k_place<<<gE, T>>>();

    // layer 1
    k_xw1<<<(NN / 4 + T - 1) / T, T>>>(x, W1);
    k_gather<<<gG, T>>>(b1);

    // hA = relu(hB) @ W2
    k_relu_w2<<<gN, T>>>(W2);

    // layer 2
    k_gather<<<gG, T>>>(b2);

    // pool + head
    k_pool<<<gN, T>>>(batch);
    k_mlp<<<NG, 128>>>(lw1, lb1, lw2, lb2, out);

    (void)in_sizes; (void)n_in; (void)out_size;
}

// round 11
// speedup vs baseline: 1.7018x; 1.0697x over previous
#include <cuda_runtime.h>

#define NN 100000
#define NE 3200000
#define NF 128
#define NH 16
#define MH 100
#define NC 12
#define NG 512

#define SCAN_CHUNK 512
#define NBLK ((NN + SCAN_CHUNK - 1) / SCAN_CHUNK)   // 196

// Scratch (allocation-free per harness rules)
__device__ __align__(16) float  g_dinv[NN];
__device__ __align__(16) int    g_degi[NN];
__device__ __align__(16) int    g_off[NN];
__device__ __align__(16) int    g_cursor[NN];
__device__ __align__(16) int    g_bsum[NBLK];
__device__ __align__(16) int    g_boff[NBLK];
__device__ __align__(16) float  g_hA[NN * NH];
__device__ __align__(16) float  g_hB[NN * NH];
__device__ __align__(16) float  g_pool[NG * NH];
__device__ __align__(16) int    g_src32[NE];
__device__ __align__(16) int    g_dst32[NE];
__device__ __align__(16) float2 g_epack[NE];   // {src bits, norm}
__device__ int g_is64;

__device__ __forceinline__ void red_add_v4(float* addr, float4 v) {
    asm volatile("red.global.add.v4.f32 [%0], {%1,%2,%3,%4};"
                 :: "l"(addr), "f"(v.x), "f"(v.y), "f"(v.z), "f"(v.w)
                 : "memory");
}

// ---------------------------------------------------------------------------
// 1) setup: dtype probe (1 thread) + degi = 0 + pool = 0
__global__ void k_setup(const int* __restrict__ ei_raw) {
    int i = blockIdx.x * blockDim.x + threadIdx.x;
    if (i == 0) {
        int ok = 1;
        #pragma unroll
        for (int j = 1; j < 32; j += 2)
            if (ei_raw[j] != 0) ok = 0;
        g_is64 = ok;
    }
    if (i < NN) g_degi[i] = 0;
    if (i < NG * NH) g_pool[i] = 0.0f;
}

// 2) fused: index conversion + degree histogram (dst side). 2 edges/thread.
__global__ void k_cvt_deg(const void* __restrict__ ei) {
    int e = (blockIdx.x * blockDim.x + threadIdx.x) * 2;
    if (e >= NE) return;  // NE % 2 == 0
    int2 s32, d32;
    if (g_is64) {
        const long long* p = (const long long*)ei;
        longlong2 s = *(const longlong2*)(p + e);
        longlong2 d = *(const longlong2*)(p + NE + e);
        s32 = make_int2((int)s.x, (int)s.y);
        d32 = make_int2((int)d.x, (int)d.y);
    } else {
        const int* p = (const int*)ei;
        s32 = *(const int2*)(p + e);
        d32 = *(const int2*)(p + NE + e);
    }
    *(int2*)(g_src32 + e) = s32;
    *(int2*)(g_dst32 + e) = d32;
    atomicAdd(&g_degi[d32.x], 1);
    atomicAdd(&g_degi[d32.y], 1);
}

// ---------------------------------------------------------------------------
// 3) scan part 1 (per-block, 512 elems) + fused dinv = rsqrt(deg+1)
__global__ void k_scan1() {
    __shared__ int s[256];
    int t = threadIdx.x, b = blockIdx.x;
    int i0 = b * SCAN_CHUNK + t * 2;
    int a = (i0     < NN) ? g_degi[i0]     : 0;
    int c = (i0 + 1 < NN) ? g_degi[i0 + 1] : 0;
    if (i0     < NN) g_dinv[i0]     = rsqrtf((float)(a + 1));
    if (i0 + 1 < NN) g_dinv[i0 + 1] = rsqrtf((float)(c + 1));
    int pair = a + c;
    s[t] = pair;
    __syncthreads();
    for (int ofs = 1; ofs < 256; ofs <<= 1) {
        int v = (t >= ofs) ? s[t - ofs] : 0;
        __syncthreads();
        s[t] += v;
        __syncthreads();
    }
    int excl = s[t] - pair;
    if (i0     < NN) g_off[i0]     = excl;
    if (i0 + 1 < NN) g_off[i0 + 1] = excl + a;
    if (t == 255) g_bsum[b] = s[255];
}

__global__ void k_scan2() {
    __shared__ int s[256];
    int t = threadIdx.x;
    int v = (t < NBLK) ? g_bsum[t] : 0;
    s[t] = v;
    __syncthreads();
    for (int ofs = 1; ofs < 256; ofs <<= 1) {
        int u = (t >= ofs) ? s[t - ofs] : 0;
        __syncthreads();
        s[t] += u;
        __syncthreads();
    }
    if (t < NBLK) g_boff[t] = s[t] - v;  // exclusive
}

__global__ void k_scan3() {
    int i = blockIdx.x * blockDim.x + threadIdx.x;
    if (i >= NN) return;
    int o = g_off[i] + g_boff[i / SCAN_CHUNK];
    g_off[i] = o;
    g_cursor[i] = o;
}

// 4) placement: bucket edges by dst, pack (src, norm)
__global__ void k_place() {
    int e = blockIdx.x * blockDim.x + threadIdx.x;
    if (e >= NE) return;
    int s = g_src32[e];
    int d = g_dst32[e];
    int pos = atomicAdd(&g_cursor[d], 1);
    float nm = g_dinv[s] * g_dinv[d];
    g_epack[pos] = make_float2(__int_as_float(s), nm);
}

// ---------------------------------------------------------------------------
// 5) g_hA = x @ W1   ([100000,128] @ [128,16]); 4 rows per thread, W1 in smem.
__global__ void k_xw1(const float* __restrict__ x, const float* __restrict__ W1) {
    __shared__ float sW[NF * NH];
    int t = threadIdx.x;
    for (int i = t; i < NF * NH; i += blockDim.x) sW[i] = W1[i];
    __syncthreads();

    int r0 = (blockIdx.x * blockDim.x + t) * 4;
    if (r0 >= NN) return;   // NN % 4 == 0

    float acc[4][NH];
    #pragma unroll
    for (int r = 0; r < 4; r++)
        #pragma unroll
        for (int m = 0; m < NH; m++) acc[r][m] = 0.0f;

    const float4* x4 = (const float4*)x;
    const float4* sW4 = (const float4*)sW;

    for (int k4 = 0; k4 < NF / 4; k4++) {
        float4 xv[4];
        #pragma unroll
        for (int r = 0; r < 4; r++)
            xv[r] = x4[(size_t)(r0 + r) * (NF / 4) + k4];

        #pragma unroll
        for (int j = 0; j < 4; j++) {
            int k = k4 * 4 + j;
            #pragma unroll
            for (int m4 = 0; m4 < NH / 4; m4++) {
                float4 wv = sW4[k * (NH / 4) + m4];
                #pragma unroll
                for (int r = 0; r < 4; r++) {
                    float xs = (j == 0) ? xv[r].x : (j == 1) ? xv[r].y
                             : (j == 2) ? xv[r].z : xv[r].w;
                    acc[r][m4 * 4 + 0] += xs * wv.x;
                    acc[r][m4 * 4 + 1] += xs * wv.y;
                    acc[r][m4 * 4 + 2] += xs * wv.z;
                    acc[r][m4 * 4 + 3] += xs * wv.w;
                }
            }
        }
    }

    #pragma unroll
    for (int r = 0; r < 4; r++) {
        float4* o = (float4*)(g_hA + (size_t)(r0 + r) * NH);
        #pragma unroll
        for (int m4 = 0; m4 < NH / 4; m4++)
            o[m4] = make_float4(acc[r][m4 * 4 + 0], acc[r][m4 * 4 + 1],
                                acc[r][m4 * 4 + 2], acc[r][m4 * 4 + 3]);
    }
}

// ---------------------------------------------------------------------------
// 6) gather1: conv1 (bias + self loop + CSR gather over g_hA), then fused
//    relu + @W2 via warp shuffles. Writes g_hB = relu(conv1) @ W2.
//    4 threads per node, groups of 4 lanes hold a full 16-feature row.
__global__ void k_gather1(const float* __restrict__ bias,
                          const float* __restrict__ W2) {
    __shared__ float sW[NH * NH];
    if (threadIdx.x < NH * NH) sW[threadIdx.x] = W2[threadIdx.x];
    __syncthreads();

    int t = blockIdx.x * blockDim.x + threadIdx.x;
    if (t >= NN * 4) return;   // NN*4 = 400000 = 12500 full warps
    int n = t >> 2;
    int c = t & 3;
    int lane = threadIdx.x & 31;

    float di = g_dinv[n];
    float d2 = di * di;
    const float4* hin = (const float4*)g_hA;
    float4 h0 = hin[n * 4 + c];
    float4 bv = ((const float4*)bias)[c];
    float4 acc = make_float4(bv.x + d2 * h0.x, bv.y + d2 * h0.y,
                             bv.z + d2 * h0.z, bv.w + d2 * h0.w);

    int beg = g_off[n];
    int end = beg + g_degi[n];
    for (int e = beg; e < end; e++) {
        float2 p = __ldg(&g_epack[e]);
        int s = __float_as_int(p.x);
        float nm = p.y;
        float4 v = __ldg(&hin[s * 4 + c]);
        acc.x += nm * v.x;
        acc.y += nm * v.y;
        acc.z += nm * v.z;
        acc.w += nm * v.w;
    }

    // relu
    float4 r = make_float4(fmaxf(acc.x, 0.f), fmaxf(acc.y, 0.f),
                           fmaxf(acc.z, 0.f), fmaxf(acc.w, 0.f));

    // collect full 16-feature row from the 4 sibling lanes
    float row[NH];
    int base = lane & ~3;
    #pragma unroll
    for (int cc = 0; cc < 4; cc++) {
        int sl = base + cc;
        row[cc * 4 + 0] = __shfl_sync(0xffffffffu, r.x, sl);
        row[cc * 4 + 1] = __shfl_sync(0xffffffffu, r.y, sl);
        row[cc * 4 + 2] = __shfl_sync(0xffffffffu, r.z, sl);
        row[cc * 4 + 3] = __shfl_sync(0xffffffffu, r.w, sl);
    }

    // out features [4c, 4c+4): o[m] = sum_k row[k] * W2[k][m]
    float4 o = make_float4(0.f, 0.f, 0.f, 0.f);
    #pragma unroll
    for (int k = 0; k < NH; k++) {
        float rk = row[k];
        const float* w = sW + k * NH + c * 4;
        o.x += rk * w[0];
        o.y += rk * w[1];
        o.z += rk * w[2];
        o.w += rk * w[3];
    }
    ((float4*)g_hB)[n * 4 + c] = o;
}

// ---------------------------------------------------------------------------
// 7) gather2: conv2 over g_hB + fused relu + global_add_pool.
//    Warp-aggregated RED into g_pool (batch sorted -> warps usually uniform).
__global__ void k_gather2(const float* __restrict__ bias,
                          const void* __restrict__ batch) {
    int t = blockIdx.x * blockDim.x + threadIdx.x;
    if (t >= NN * 4) return;   // warp-aligned boundary
    int n = t >> 2;
    int c = t & 3;
    int lane = threadIdx.x & 31;

    float di = g_dinv[n];
    float d2 = di * di;
    const float4* hin = (const float4*)g_hB;
    float4 h0 = hin[n * 4 + c];
    float4 bv = ((const float4*)bias)[c];
    float4 acc = make_float4(bv.x + d2 * h0.x, bv.y + d2 * h0.y,
                             bv.z + d2 * h0.z, bv.w + d2 * h0.w);

    int beg = g_off[n];
    int end = beg + g_degi[n];
    for (int e = beg; e < end; e++) {
        float2 p = __ldg(&g_epack[e]);
        int s = __float_as_int(p.x);
        float nm = p.y;
        float4 v = __ldg(&hin[s * 4 + c]);
        acc.x += nm * v.x;
        acc.y += nm * v.y;
        acc.z += nm * v.z;
        acc.w += nm * v.w;
    }

    float4 r = make_float4(fmaxf(acc.x, 0.f), fmaxf(acc.y, 0.f),
                           fmaxf(acc.z, 0.f), fmaxf(acc.w, 0.f));

    int b;
    if (g_is64) b = (int)((const long long*)batch)[n];
    else        b = ((const int*)batch)[n];

    // warp aggregation: if all 8 nodes in warp share one graph, reduce the
    // 8 same-chunk lanes and let lanes 0..3 emit a single RED each.
    int b0 = __shfl_sync(0xffffffffu, b, 0);
    bool uniform = __all_sync(0xffffffffu, b == b0);
    if (uniform) {
        #pragma unroll
        for (int m = 16; m >= 4; m >>= 1) {
            r.x += __shfl_xor_sync(0xffffffffu, r.x, m);
            r.y += __shfl_xor_sync(0xffffffffu, r.y, m);
            r.z += __shfl_xor_sync(0xffffffffu, r.z, m);
            r.w += __shfl_xor_sync(0xffffffffu, r.w, m);
        }
        if (lane < 4)
            red_add_v4(g_pool + (size_t)b0 * NH + lane * 4, r);
    } else {
        red_add_v4(g_pool + (size_t)b * NH + c * 4, r);
    }
}

// ---------------------------------------------------------------------------
// 8) MLP head: out = relu(relu(pool) @ lw1 + lb1) @ lw2 + lb2
__global__ void k_mlp(const float* __restrict__ lw1, const float* __restrict__ lb1,
                      const float* __restrict__ lw2, const float* __restrict__ lb2,
                      float* __restrict__ out) {
    __shared__ float sg[NH];
    __shared__ float sh[MH];
    int g = blockIdx.x;
    int t = threadIdx.x;
    if (t < NH) sg[t] = fmaxf(g_pool[(size_t)g * NH + t], 0.0f);
    __syncthreads();
    if (t < MH) {
        float a = lb1[t];
        #pragma unroll
        for (int i = 0; i < NH; i++) a += sg[i] * lw1[i * MH + t];
        sh[t] = fmaxf(a, 0.0f);
    }
    __syncthreads();
    if (t < NC) {
        float a = lb2[t];
        #pragma unroll 4
        for (int i = 0; i < MH; i++) a += sh[i] * lw2[i * NC + t];
        out[(size_t)g * NC + t] = a;
    }
}

// ---------------------------------------------------------------------------
extern "C" void kernel_launch(void* const* d_in, const int* in_sizes, int n_in,
                              void* d_out, int out_size) {
    const float* x     = (const float*)d_in[0];
    const void*  ei    = d_in[1];
    const void*  batch = d_in[2];
    const float* W1    = (const float*)d_in[3];
    const float* b1    = (const float*)d_in[4];
    const float* W2    = (const float*)d_in[5];
    const float* b2    = (const float*)d_in[6];
    const float* lw1   = (const float*)d_in[7];
    const float* lb1   = (const float*)d_in[8];
    const float* lw2   = (const float*)d_in[9];
    const float* lb2   = (const float*)d_in[10];
    float* out = (float*)d_out;

    const int T = 256;
    const int gN  = (NN + T - 1) / T;
    const int gE  = (NE + T - 1) / T;
    const int gE2 = (NE / 2 + T - 1) / T;
    const int gG  = (NN * 4 + T - 1) / T;

    k_setup<<<gN, T>>>((const int*)ei);
    k_cvt_deg<<<gE2, T>>>(ei);

    // CSR build (+ dinv fused into scan1)
    k_scan1<<<NBLK, 256>>>();
    k_scan2<<<1, 256>>>();
    k_scan3<<<gN, T>>>();
    k_place<<<gE, T>>>();

    // layer 1 (+ fused relu @ W2)
    k_xw1<<<(NN / 4 + T - 1) / T, T>>>(x, W1);
    k_gather1<<<gG, T>>>(b1, W2);

    // layer 2 (+ fused relu + pool)
    k_gather2<<<gG, T>>>(b2, batch);

    // head
    k_mlp<<<NG, 128>>>(lw1, lb1, lw2, lb2, out);

    (void)in_sizes; (void)n_in; (void)out_size;
}